// round 2
// baseline (speedup 1.0000x reference)
#include <cuda_runtime.h>
#include <math.h>

// Problem dims (fixed by the reference)
#define B_  256
#define T_  256
#define I_  64
#define H_  2048
#define L_  4
#define BH_ (B_ * H_)          // 524288 elements per time-slice

// Scratch (device globals: allocation-free contract).
__device__ float g_XT[(size_t)T_ * B_ * I_];     // 16 MB  : x transposed to [T,B,I]
__device__ float g_XP[(size_t)T_ * B_ * H_];     // 512 MB : input projections
__device__ float g_SEQ[(size_t)T_ * B_ * H_];    // 512 MB : hidden sequence
__device__ unsigned int g_bar;                   // grid-barrier counter (memset per run)

// ---------------------------------------------------------------------------
// x[B,T,I] -> XT[T,B,I]  (float4 granularity, I=64 -> 16 float4 per row)
// ---------------------------------------------------------------------------
__global__ void transpose_x(const float* __restrict__ x, float* __restrict__ xt) {
    int idx = blockIdx.x * blockDim.x + threadIdx.x;   // over T*B*16
    int i4 = idx & 15;
    int b  = (idx >> 4) & (B_ - 1);
    int t  = idx >> 12;
    float4 v = *(const float4*)(x + ((size_t)b * T_ + t) * I_ + i4 * 4);
    *(float4*)(xt + ((size_t)t * B_ + b) * I_ + i4 * 4) = v;
}

// ---------------------------------------------------------------------------
// Generic "NT" tiled SGEMM for the time-parallel projections:
//   C[m,n] = A[m,k]*W[n,k] + bias[n]
// ---------------------------------------------------------------------------
template<int BM, int BN, int BK, int TM, int TN>
__global__ __launch_bounds__((BM / TM) * (BN / TN))
void gemm_nt(const float* __restrict__ A, const float* __restrict__ W,
             const float* __restrict__ bias, float* __restrict__ C,
             int M, int N, int K)
{
    constexpr int NT  = (BM / TM) * (BN / TN);   // 256 threads
    constexpr int KV  = BK / 4;
    constexpr int AV  = (BM * BK) / (NT * 4);
    constexpr int BV  = (BN * BK) / (NT * 4);
    constexpr int ARS = NT / KV;

    __shared__ __align__(16) float As[BK][BM + 4];
    __shared__ __align__(16) float Bs[BK][BN + 4];

    const int tid = threadIdx.x;
    const int bm  = blockIdx.y * BM;
    const int bn  = blockIdx.x * BN;

    const int lr = tid / KV;
    const int lc = (tid % KV) * 4;

    const float* Ag = A + (size_t)(bm + lr) * K + lc;
    const float* Wg = W + (size_t)(bn + lr) * K + lc;

    const int tx = tid % (BN / TN);
    const int ty = tid / (BN / TN);

    float acc[TM][TN];
    #pragma unroll
    for (int i = 0; i < TM; i++)
        #pragma unroll
        for (int j = 0; j < TN; j++) acc[i][j] = 0.f;

    float4 ra[AV], rb[BV];
    #pragma unroll
    for (int v = 0; v < AV; v++) ra[v] = *(const float4*)(Ag + (size_t)v * ARS * K);
    #pragma unroll
    for (int v = 0; v < BV; v++) rb[v] = *(const float4*)(Wg + (size_t)v * ARS * K);

    for (int k0 = 0; k0 < K; k0 += BK) {
        __syncthreads();
        #pragma unroll
        for (int v = 0; v < AV; v++) {
            As[lc + 0][lr + v * ARS] = ra[v].x;
            As[lc + 1][lr + v * ARS] = ra[v].y;
            As[lc + 2][lr + v * ARS] = ra[v].z;
            As[lc + 3][lr + v * ARS] = ra[v].w;
        }
        #pragma unroll
        for (int v = 0; v < BV; v++) {
            Bs[lc + 0][lr + v * ARS] = rb[v].x;
            Bs[lc + 1][lr + v * ARS] = rb[v].y;
            Bs[lc + 2][lr + v * ARS] = rb[v].z;
            Bs[lc + 3][lr + v * ARS] = rb[v].w;
        }
        __syncthreads();

        if (k0 + BK < K) {
            #pragma unroll
            for (int v = 0; v < AV; v++)
                ra[v] = *(const float4*)(Ag + (size_t)v * ARS * K + k0 + BK);
            #pragma unroll
            for (int v = 0; v < BV; v++)
                rb[v] = *(const float4*)(Wg + (size_t)v * ARS * K + k0 + BK);
        }

        #pragma unroll
        for (int kk = 0; kk < BK; ++kk) {
            float a[TM], b[TN];
            #pragma unroll
            for (int i = 0; i < TM; i += 4)
                *(float4*)&a[i] = *(const float4*)&As[kk][ty * TM + i];
            #pragma unroll
            for (int j = 0; j < TN; j += 4)
                *(float4*)&b[j] = *(const float4*)&Bs[kk][tx * TN + j];
            #pragma unroll
            for (int i = 0; i < TM; i++)
                #pragma unroll
                for (int j = 0; j < TN; j++)
                    acc[i][j] = fmaf(a[i], b[j], acc[i][j]);
        }
    }

    const int n0 = bn + tx * TN;
    float4 bia = *(const float4*)(bias + n0);
    #pragma unroll
    for (int i = 0; i < TM; i++) {
        const size_t row = (size_t)(bm + ty * TM + i) * N + n0;
        float4 v;
        v.x = acc[i][0] + bia.x; v.y = acc[i][1] + bia.y;
        v.z = acc[i][2] + bia.z; v.w = acc[i][3] + bia.w;
        *(float4*)(C + row) = v;
    }
}

// ---------------------------------------------------------------------------
// Persistent per-layer scan kernel.
// grid = 128 CTAs (4 m-tiles x 32 n-tiles), 256 threads, 1 CTA/SM -> all
// co-resident, so a software grid barrier between time steps is safe.
// Step t: SEQ[t] = tanh(XP[t] + SEQ[t-1] @ W^T)   (t=0: tanh(XP[0]))
// Barrier counter is monotonic across the 4 layer launches within one run;
// `base` = number of barriers completed by previous layers.
// ---------------------------------------------------------------------------
#define SCAN_NB 128

__device__ __forceinline__ void grid_barrier(unsigned int target) {
    __syncthreads();
    if (threadIdx.x == 0) {
        __threadfence();
        atomicAdd(&g_bar, 1u);
        while (*((volatile unsigned int*)&g_bar) < target) { }
        __threadfence();
    }
    __syncthreads();
}

__global__ __launch_bounds__(256, 1)
void scan_layer(const float* __restrict__ XP, float* __restrict__ SEQ,
                const float* __restrict__ W, unsigned int base)
{
    constexpr int BK = 16;
    __shared__ __align__(16) float As[BK][64 + 4];
    __shared__ __align__(16) float Bs[BK][64 + 4];

    const int tid = threadIdx.x;
    const int bm  = (blockIdx.x >> 5) * 64;        // 4 m-tiles (B=256)
    const int bn  = (blockIdx.x & 31) * 64;        // 32 n-tiles (H=2048)

    const int lr = tid / (BK / 4);                 // 0..63
    const int lc = (tid % (BK / 4)) * 4;           // k offset in slab
    const int tx = tid & 15;                       // n sub-tile (TN=4)
    const int ty = tid >> 4;                       // m sub-tile (TM=4)

    // ---- t = 0: SEQ[0] = tanh(XP[0]) on this tile --------------------------
    for (int i = tid; i < 1024; i += 256) {        // 64*64/4 float4s
        int r = i >> 4, c = (i & 15) * 4;
        size_t off = (size_t)(bm + r) * H_ + bn + c;
        float4 v = *(const float4*)(XP + off);
        v.x = tanhf(v.x); v.y = tanhf(v.y); v.z = tanhf(v.z); v.w = tanhf(v.w);
        *(float4*)(SEQ + off) = v;
    }
    grid_barrier((base + 1) * SCAN_NB);

    const float* Wg = W + (size_t)(bn + lr) * H_ + lc;

    // ---- t = 1 .. T-1 ------------------------------------------------------
    for (int t = 1; t < T_; ++t) {
        const float* Aprev = SEQ + (size_t)(t - 1) * BH_;
        const float* Ag    = Aprev + (size_t)(bm + lr) * H_ + lc;

        float acc[4][4];
        #pragma unroll
        for (int i = 0; i < 4; i++)
            #pragma unroll
            for (int j = 0; j < 4; j++) acc[i][j] = 0.f;

        float4 ra = *(const float4*)(Ag);
        float4 rb = *(const float4*)(Wg);

        for (int k0 = 0; k0 < H_; k0 += BK) {
            __syncthreads();
            As[lc + 0][lr] = ra.x; As[lc + 1][lr] = ra.y;
            As[lc + 2][lr] = ra.z; As[lc + 3][lr] = ra.w;
            Bs[lc + 0][lr] = rb.x; Bs[lc + 1][lr] = rb.y;
            Bs[lc + 2][lr] = rb.z; Bs[lc + 3][lr] = rb.w;
            __syncthreads();

            if (k0 + BK < H_) {
                ra = *(const float4*)(Ag + k0 + BK);
                rb = *(const float4*)(Wg + k0 + BK);
            }

            #pragma unroll
            for (int kk = 0; kk < BK; ++kk) {
                float a[4], b[4];
                *(float4*)&a[0] = *(const float4*)&As[kk][ty * 4];
                *(float4*)&b[0] = *(const float4*)&Bs[kk][tx * 4];
                #pragma unroll
                for (int i = 0; i < 4; i++)
                    #pragma unroll
                    for (int j = 0; j < 4; j++)
                        acc[i][j] = fmaf(a[i], b[j], acc[i][j]);
            }
        }

        // Epilogue: + XP[t], tanh, write SEQ[t]
        const float* XPt = XP + (size_t)t * BH_;
        float* SEQt      = SEQ + (size_t)t * BH_;
        const int n0 = bn + tx * 4;
        #pragma unroll
        for (int i = 0; i < 4; i++) {
            const size_t row = (size_t)(bm + ty * 4 + i) * H_ + n0;
            float4 c = *(const float4*)(XPt + row);
            float4 v;
            v.x = tanhf(acc[i][0] + c.x);
            v.y = tanhf(acc[i][1] + c.y);
            v.z = tanhf(acc[i][2] + c.z);
            v.w = tanhf(acc[i][3] + c.w);
            *(float4*)(SEQt + row) = v;
        }
        grid_barrier((base + t + 1) * SCAN_NB);
    }
}

// ---------------------------------------------------------------------------
// Final FC: out[b] = sum_j h[b,j] * w[j] + b_fc   (O == 1)
// ---------------------------------------------------------------------------
__global__ void fc_kernel(const float* __restrict__ h, const float* __restrict__ w,
                          const float* __restrict__ bfc, float* __restrict__ out) {
    __shared__ float red[256];
    const float* row = h + (size_t)blockIdx.x * H_;
    float s = 0.f;
    for (int j = threadIdx.x; j < H_; j += 256) s = fmaf(row[j], w[j], s);
    red[threadIdx.x] = s;
    __syncthreads();
    for (int off = 128; off; off >>= 1) {
        if (threadIdx.x < off) red[threadIdx.x] += red[threadIdx.x + off];
        __syncthreads();
    }
    if (threadIdx.x == 0) out[blockIdx.x] = red[0] + bfc[0];
}

// ---------------------------------------------------------------------------
extern "C" void kernel_launch(void* const* d_in, const int* in_sizes, int n_in,
                              void* d_out, int out_size)
{
    const float* x      = (const float*)d_in[0];  // [B,T,I]
    const float* W_ih0  = (const float*)d_in[1];  // [H,I]
    const float* b_ih0  = (const float*)d_in[2];  // [H]
    const float* W_ihr  = (const float*)d_in[3];  // [L-1,H,H]
    const float* b_ihr  = (const float*)d_in[4];  // [L-1,H]
    const float* W_hh   = (const float*)d_in[5];  // [L,H,H]
    const float* W_fc   = (const float*)d_in[6];  // [1,H]
    const float* b_fc   = (const float*)d_in[7];  // [1]
    float* out = (float*)d_out;

    float *XT, *XP, *SEQ;
    unsigned int* bar;
    cudaGetSymbolAddress((void**)&XT,  g_XT);
    cudaGetSymbolAddress((void**)&XP,  g_XP);
    cudaGetSymbolAddress((void**)&SEQ, g_SEQ);
    cudaGetSymbolAddress((void**)&bar, g_bar);

    cudaMemsetAsync(bar, 0, sizeof(unsigned int));   // reset barrier counter

    transpose_x<<<(T_ * B_ * (I_ / 4)) / 256, 256>>>(x, XT);

    for (int l = 0; l < L_; ++l) {
        if (l == 0) {
            gemm_nt<128, 64, 16, 8, 4>
                <<<dim3(H_ / 64, (T_ * B_) / 128), 256>>>(
                    XT, W_ih0, b_ih0, XP, T_ * B_, H_, I_);
        } else {
            gemm_nt<128, 64, 16, 8, 4>
                <<<dim3(H_ / 64, (T_ * B_) / 128), 256>>>(
                    SEQ, W_ihr + (size_t)(l - 1) * H_ * H_,
                    b_ihr + (size_t)(l - 1) * H_, XP, T_ * B_, H_, H_);
        }
        scan_layer<<<SCAN_NB, 256>>>(XP, SEQ, W_hh + (size_t)l * H_ * H_,
                                     (unsigned int)(l * T_));
    }

    fc_kernel<<<B_, 256>>>(SEQ + (size_t)(T_ - 1) * BH_, W_fc, b_fc, out);
}

// round 3
// speedup vs baseline: 2.6102x; 2.6102x over previous
#include <cuda_runtime.h>
#include <cuda_bf16.h>
#include <math.h>

#define B_  256
#define T_  256
#define I_  64
#define H_  2048
#define L_  4
#define BH_ (B_ * H_)
#define K2_ 4096

// ---- wave kernel tiling ----
#define PITCH   72                       // bf16 elems per smem row (144B, conflict-free)
#define TILE_E  (128 * PITCH)            // one operand tile (elems)
#define STAGE_E (4 * TILE_E)             // Ah, Al, Bh, Bl
#define SMEM_BYTES (2 * STAGE_E * 2)     // 2 stages, 2B/elem = 147456

// ---- device scratch (allocation-free contract) ----
__device__ float g_XT[(size_t)T_ * B_ * I_];
__device__ float g_XP[(size_t)T_ * B_ * H_];                 // layer-0 input projection
__device__ __nv_bfloat16 g_W0h[(size_t)H_ * H_];
__device__ __nv_bfloat16 g_W0l[(size_t)H_ * H_];
__device__ __nv_bfloat16 g_Wch[(size_t)3 * H_ * K2_];        // [Wih ; Whh] concat, layers 1..3
__device__ __nv_bfloat16 g_Wcl[(size_t)3 * H_ * K2_];
__device__ __nv_bfloat16 g_Hh[(size_t)L_ * 2 * BH_];         // h ping-pong, hi part
__device__ __nv_bfloat16 g_Hl[(size_t)L_ * 2 * BH_];         // lo part
__device__ unsigned g_bar;

// ---------------------------------------------------------------------------
// helpers
// ---------------------------------------------------------------------------
__device__ __forceinline__ unsigned sptr(const void* p) {
    return (unsigned)__cvta_generic_to_shared(p);
}
__device__ __forceinline__ void cp16(__nv_bfloat16* s, const __nv_bfloat16* g) {
    asm volatile("cp.async.cg.shared.global [%0], [%1], 16;" :: "r"(sptr(s)), "l"(g));
}
__device__ __forceinline__ void ldsm4(unsigned& r0, unsigned& r1, unsigned& r2,
                                      unsigned& r3, const __nv_bfloat16* p) {
    asm volatile("ldmatrix.sync.aligned.m8n8.x4.shared.b16 {%0,%1,%2,%3}, [%4];"
                 : "=r"(r0), "=r"(r1), "=r"(r2), "=r"(r3) : "r"(sptr(p)));
}
__device__ __forceinline__ void mma16816(float* d, const unsigned* a, const unsigned* b) {
    asm volatile("mma.sync.aligned.m16n8k16.row.col.f32.bf16.bf16.f32 "
                 "{%0,%1,%2,%3}, {%4,%5,%6,%7}, {%8,%9}, {%0,%1,%2,%3};"
                 : "+f"(d[0]), "+f"(d[1]), "+f"(d[2]), "+f"(d[3])
                 : "r"(a[0]), "r"(a[1]), "r"(a[2]), "r"(a[3]), "r"(b[0]), "r"(b[1]));
}

// ---------------------------------------------------------------------------
// x[B,T,I] -> XT[T,B,I]
// ---------------------------------------------------------------------------
__global__ void transpose_x(const float* __restrict__ x, float* __restrict__ xt) {
    int idx = blockIdx.x * blockDim.x + threadIdx.x;
    int i4 = idx & 15;
    int b  = (idx >> 4) & (B_ - 1);
    int t  = idx >> 12;
    float4 v = *(const float4*)(x + ((size_t)b * T_ + t) * I_ + i4 * 4);
    *(float4*)(xt + ((size_t)t * B_ + b) * I_ + i4 * 4) = v;
}

// ---------------------------------------------------------------------------
// fp32 NT GEMM (layer-0 input projection only, K=64):  C = A@W^T + bias
// ---------------------------------------------------------------------------
template<int BM, int BN, int BK, int TM, int TN>
__global__ __launch_bounds__((BM / TM) * (BN / TN))
void gemm_nt(const float* __restrict__ A, const float* __restrict__ W,
             const float* __restrict__ bias, float* __restrict__ C,
             int M, int N, int K)
{
    constexpr int NT  = (BM / TM) * (BN / TN);
    constexpr int KV  = BK / 4;
    constexpr int AV  = (BM * BK) / (NT * 4);
    constexpr int BV  = (BN * BK) / (NT * 4);
    constexpr int ARS = NT / KV;

    __shared__ __align__(16) float As[BK][BM + 4];
    __shared__ __align__(16) float Bs[BK][BN + 4];

    const int tid = threadIdx.x;
    const int bm  = blockIdx.y * BM;
    const int bn  = blockIdx.x * BN;
    const int lr = tid / KV;
    const int lc = (tid % KV) * 4;
    const float* Ag = A + (size_t)(bm + lr) * K + lc;
    const float* Wg = W + (size_t)(bn + lr) * K + lc;
    const int tx = tid % (BN / TN);
    const int ty = tid / (BN / TN);

    float acc[TM][TN];
    #pragma unroll
    for (int i = 0; i < TM; i++)
        #pragma unroll
        for (int j = 0; j < TN; j++) acc[i][j] = 0.f;

    float4 ra[AV], rb[BV];
    #pragma unroll
    for (int v = 0; v < AV; v++) ra[v] = *(const float4*)(Ag + (size_t)v * ARS * K);
    #pragma unroll
    for (int v = 0; v < BV; v++) rb[v] = *(const float4*)(Wg + (size_t)v * ARS * K);

    for (int k0 = 0; k0 < K; k0 += BK) {
        __syncthreads();
        #pragma unroll
        for (int v = 0; v < AV; v++) {
            As[lc + 0][lr + v * ARS] = ra[v].x; As[lc + 1][lr + v * ARS] = ra[v].y;
            As[lc + 2][lr + v * ARS] = ra[v].z; As[lc + 3][lr + v * ARS] = ra[v].w;
        }
        #pragma unroll
        for (int v = 0; v < BV; v++) {
            Bs[lc + 0][lr + v * ARS] = rb[v].x; Bs[lc + 1][lr + v * ARS] = rb[v].y;
            Bs[lc + 2][lr + v * ARS] = rb[v].z; Bs[lc + 3][lr + v * ARS] = rb[v].w;
        }
        __syncthreads();
        if (k0 + BK < K) {
            #pragma unroll
            for (int v = 0; v < AV; v++) ra[v] = *(const float4*)(Ag + (size_t)v * ARS * K + k0 + BK);
            #pragma unroll
            for (int v = 0; v < BV; v++) rb[v] = *(const float4*)(Wg + (size_t)v * ARS * K + k0 + BK);
        }
        #pragma unroll
        for (int kk = 0; kk < BK; ++kk) {
            float a[TM], b[TN];
            #pragma unroll
            for (int i = 0; i < TM; i += 4) *(float4*)&a[i] = *(const float4*)&As[kk][ty * TM + i];
            #pragma unroll
            for (int j = 0; j < TN; j += 4) *(float4*)&b[j] = *(const float4*)&Bs[kk][tx * TN + j];
            #pragma unroll
            for (int i = 0; i < TM; i++)
                #pragma unroll
                for (int j = 0; j < TN; j++) acc[i][j] = fmaf(a[i], b[j], acc[i][j]);
        }
    }
    const int n0 = bn + tx * TN;
    float4 bia = *(const float4*)(bias + n0);
    #pragma unroll
    for (int i = 0; i < TM; i++) {
        const size_t row = (size_t)(bm + ty * TM + i) * N + n0;
        float4 v;
        v.x = acc[i][0] + bia.x; v.y = acc[i][1] + bia.y;
        v.z = acc[i][2] + bia.z; v.w = acc[i][3] + bia.w;
        *(float4*)(C + row) = v;
    }
}

// ---------------------------------------------------------------------------
// weight precompute: fp32 -> bf16 hi/lo split
// ---------------------------------------------------------------------------
__global__ void split_w0(const float* __restrict__ W,
                         __nv_bfloat16* __restrict__ h, __nv_bfloat16* __restrict__ lo) {
    size_t i = (size_t)blockIdx.x * blockDim.x + threadIdx.x;  // H*H
    float v = W[i];
    __nv_bfloat16 a = __float2bfloat16(v);
    h[i]  = a;
    lo[i] = __float2bfloat16(v - __bfloat162float(a));
}

__global__ void build_wcat(const float* __restrict__ Wihr, const float* __restrict__ Whh,
                           __nv_bfloat16* __restrict__ ch, __nv_bfloat16* __restrict__ cl) {
    size_t i = (size_t)blockIdx.x * blockDim.x + threadIdx.x;  // 3*H*K2
    int lw = (int)(i / ((size_t)H_ * K2_));
    size_t rem = i % ((size_t)H_ * K2_);
    int n = (int)(rem / K2_);
    int k = (int)(rem % K2_);
    float v = (k < H_) ? Wihr[(size_t)lw * H_ * H_ + (size_t)n * H_ + k]
                       : Whh[(size_t)(lw + 1) * H_ * H_ + (size_t)n * H_ + (k - H_)];
    __nv_bfloat16 a = __float2bfloat16(v);
    ch[i] = a;
    cl[i] = __float2bfloat16(v - __bfloat162float(a));
}

// ---------------------------------------------------------------------------
// Persistent wavefront kernel: 128 CTAs = 4 layers x (2 m-tiles x 16 n-tiles),
// CTA tile 128x128, bf16x3 split MMA, K streamed in 64-chunks (cp.async x2).
// Step s computes h^l_{s-l}; grid barrier between steps.
// ---------------------------------------------------------------------------
__device__ __forceinline__ void grid_barrier(unsigned target) {
    __threadfence();
    __syncthreads();
    if (threadIdx.x == 0) {
        atomicAdd(&g_bar, 1u);
        while (*((volatile unsigned*)&g_bar) < target) { }
        __threadfence();
    }
    __syncthreads();
}

__global__ __launch_bounds__(256, 1)
void wave_kernel(const float* __restrict__ XP0, const float* __restrict__ b_ihr)
{
    extern __shared__ __nv_bfloat16 sm[];
    const int tid  = threadIdx.x;
    const int warp = tid >> 5, lane = tid & 31;
    const int l  = blockIdx.x >> 5;
    const int rr = blockIdx.x & 31;
    const int bm = (rr & 1) * 128;
    const int bn = (rr >> 1) * 128;

    const int Kl = (l == 0) ? H_ : K2_;
    const __nv_bfloat16* WBh = (l == 0) ? (g_W0h + (size_t)bn * H_)
                                        : (g_Wch + (size_t)(l - 1) * H_ * K2_ + (size_t)bn * K2_);
    const __nv_bfloat16* WBl = (l == 0) ? (g_W0l + (size_t)bn * H_)
                                        : (g_Wcl + (size_t)(l - 1) * H_ * K2_ + (size_t)bn * K2_);

    const int wm = (warp & 1) * 64;     // warp tile 64x32
    const int wn = (warp >> 1) * 32;
    // ldmatrix lane address components
    const int a_row = lane & 15;
    const int a_k   = (lane >> 4) * 8;
    const int b_row = (lane & 7) + ((lane >> 4) << 3);
    const int b_k   = ((lane >> 3) & 1) * 8;
    // cp.async lane components (4 iters cover 128 rows x 64 elems)
    const int ldrow = tid >> 3;
    const int ldc   = (tid & 7) * 8;

    for (int s = 0; s < T_ + L_ - 1; ++s) {
        const int t = s - l;
        if (t >= 0 && t < T_) {
            const int kEnd = (l == 0) ? (t == 0 ? 0 : H_) : (t == 0 ? H_ : K2_);

            float acc[4][4][4];
            #pragma unroll
            for (int i = 0; i < 4; i++)
                #pragma unroll
                for (int j = 0; j < 4; j++)
                    #pragma unroll
                    for (int q = 0; q < 4; q++) acc[i][j][q] = 0.f;

            auto load_chunk = [&](int stg, int k0) {
                __nv_bfloat16* base = sm + stg * STAGE_E;
                const __nv_bfloat16 *Ah_g, *Al_g;
                int ak;
                if (l == 0) {                       // A = h^0_{t-1}
                    size_t off = (size_t)(0 * 2 + ((t - 1) & 1)) * BH_;
                    Ah_g = g_Hh + off; Al_g = g_Hl + off; ak = k0;
                } else if (k0 < H_) {               // A = h^{l-1}_t
                    size_t off = (size_t)((l - 1) * 2 + (t & 1)) * BH_;
                    Ah_g = g_Hh + off; Al_g = g_Hl + off; ak = k0;
                } else {                            // A = h^l_{t-1}
                    size_t off = (size_t)(l * 2 + ((t - 1) & 1)) * BH_;
                    Ah_g = g_Hh + off; Al_g = g_Hl + off; ak = k0 - H_;
                }
                #pragma unroll
                for (int i = 0; i < 4; i++) {
                    int row = ldrow + i * 32;
                    size_t ga = (size_t)(bm + row) * H_ + ak + ldc;
                    size_t gb = (size_t)row * Kl + k0 + ldc;
                    int so = row * PITCH + ldc;
                    cp16(base + so,              Ah_g + ga);
                    cp16(base + TILE_E + so,     Al_g + ga);
                    cp16(base + 2 * TILE_E + so, WBh + gb);
                    cp16(base + 3 * TILE_E + so, WBl + gb);
                }
                asm volatile("cp.async.commit_group;");
            };

            auto compute = [&](int stg) {
                const __nv_bfloat16* base = sm + stg * STAGE_E;
                #pragma unroll
                for (int kk = 0; kk < 4; kk++) {
                    unsigned ah[4][4], al[4][4], bh[4][2], bl[4][2];
                    #pragma unroll
                    for (int i = 0; i < 4; i++) {
                        const __nv_bfloat16* pa =
                            base + (wm + i * 16 + a_row) * PITCH + kk * 16 + a_k;
                        ldsm4(ah[i][0], ah[i][1], ah[i][2], ah[i][3], pa);
                        ldsm4(al[i][0], al[i][1], al[i][2], al[i][3], pa + TILE_E);
                    }
                    #pragma unroll
                    for (int jp = 0; jp < 2; jp++) {
                        const __nv_bfloat16* pb =
                            base + 2 * TILE_E + (wn + jp * 16 + b_row) * PITCH + kk * 16 + b_k;
                        unsigned r0, r1, r2, r3;
                        ldsm4(r0, r1, r2, r3, pb);
                        bh[jp * 2][0] = r0; bh[jp * 2][1] = r1;
                        bh[jp * 2 + 1][0] = r2; bh[jp * 2 + 1][1] = r3;
                        ldsm4(r0, r1, r2, r3, pb + TILE_E);
                        bl[jp * 2][0] = r0; bl[jp * 2][1] = r1;
                        bl[jp * 2 + 1][0] = r2; bl[jp * 2 + 1][1] = r3;
                    }
                    #pragma unroll
                    for (int i = 0; i < 4; i++)
                        #pragma unroll
                        for (int j = 0; j < 4; j++) {
                            mma16816(acc[i][j], ah[i], bh[j]);
                            mma16816(acc[i][j], ah[i], bl[j]);
                            mma16816(acc[i][j], al[i], bh[j]);
                        }
                }
            };

            if (kEnd > 0) {
                load_chunk(0, 0);
                const int NC = kEnd / 64;
                for (int c = 0; c < NC; c++) {
                    if (c + 1 < NC) {
                        load_chunk((c + 1) & 1, (c + 1) * 64);
                        asm volatile("cp.async.wait_group 1;");
                    } else {
                        asm volatile("cp.async.wait_group 0;");
                    }
                    __syncthreads();
                    compute(c & 1);
                    __syncthreads();
                }
            }

            // epilogue: +XP0 (l==0) or +bias, tanh, bf16 hi/lo split store
            {
                const size_t hoff = (size_t)(l * 2 + (t & 1)) * BH_;
                #pragma unroll
                for (int i = 0; i < 4; i++) {
                    const int m0 = bm + wm + i * 16 + (lane >> 2);
                    #pragma unroll
                    for (int j = 0; j < 4; j++) {
                        const int n0 = bn + wn + j * 8 + (lane & 3) * 2;
                        float a0, a1, a2, a3;
                        if (l == 0) {
                            const float* xp = XP0 + (size_t)t * BH_;
                            float2 u = *(const float2*)(xp + (size_t)m0 * H_ + n0);
                            float2 w = *(const float2*)(xp + (size_t)(m0 + 8) * H_ + n0);
                            a0 = u.x; a1 = u.y; a2 = w.x; a3 = w.y;
                        } else {
                            float2 u = *(const float2*)(b_ihr + (size_t)(l - 1) * H_ + n0);
                            a0 = u.x; a1 = u.y; a2 = u.x; a3 = u.y;
                        }
                        float v0 = tanhf(acc[i][j][0] + a0);
                        float v1 = tanhf(acc[i][j][1] + a1);
                        float v2 = tanhf(acc[i][j][2] + a2);
                        float v3 = tanhf(acc[i][j][3] + a3);

                        __nv_bfloat16 h0 = __float2bfloat16(v0), h1 = __float2bfloat16(v1);
                        __nv_bfloat16 h2 = __float2bfloat16(v2), h3 = __float2bfloat16(v3);
                        __nv_bfloat162 ph, pl;
                        ph.x = h0; ph.y = h1;
                        pl.x = __float2bfloat16(v0 - __bfloat162float(h0));
                        pl.y = __float2bfloat16(v1 - __bfloat162float(h1));
                        *(__nv_bfloat162*)(g_Hh + hoff + (size_t)m0 * H_ + n0) = ph;
                        *(__nv_bfloat162*)(g_Hl + hoff + (size_t)m0 * H_ + n0) = pl;
                        ph.x = h2; ph.y = h3;
                        pl.x = __float2bfloat16(v2 - __bfloat162float(h2));
                        pl.y = __float2bfloat16(v3 - __bfloat162float(h3));
                        *(__nv_bfloat162*)(g_Hh + hoff + (size_t)(m0 + 8) * H_ + n0) = ph;
                        *(__nv_bfloat162*)(g_Hl + hoff + (size_t)(m0 + 8) * H_ + n0) = pl;
                    }
                }
            }
        }
        grid_barrier((unsigned)(s + 1) * 128u);
    }
}

// ---------------------------------------------------------------------------
// Final FC: out[b] = (hi+lo)[b,:] @ W_fc^T + b_fc
// ---------------------------------------------------------------------------
__global__ void fc_kernel(const __nv_bfloat16* __restrict__ hh,
                          const __nv_bfloat16* __restrict__ hl,
                          const float* __restrict__ w, const float* __restrict__ bfc,
                          float* __restrict__ out) {
    __shared__ float red[256];
    const size_t base = (size_t)blockIdx.x * H_;
    float s = 0.f;
    for (int j = threadIdx.x; j < H_; j += 256) {
        float hv = __bfloat162float(hh[base + j]) + __bfloat162float(hl[base + j]);
        s = fmaf(hv, w[j], s);
    }
    red[threadIdx.x] = s;
    __syncthreads();
    for (int off = 128; off; off >>= 1) {
        if (threadIdx.x < off) red[threadIdx.x] += red[threadIdx.x + off];
        __syncthreads();
    }
    if (threadIdx.x == 0) out[blockIdx.x] = red[0] + bfc[0];
}

// ---------------------------------------------------------------------------
extern "C" void kernel_launch(void* const* d_in, const int* in_sizes, int n_in,
                              void* d_out, int out_size)
{
    const float* x      = (const float*)d_in[0];
    const float* W_ih0  = (const float*)d_in[1];
    const float* b_ih0  = (const float*)d_in[2];
    const float* W_ihr  = (const float*)d_in[3];
    const float* b_ihr  = (const float*)d_in[4];
    const float* W_hh   = (const float*)d_in[5];
    const float* W_fc   = (const float*)d_in[6];
    const float* b_fc   = (const float*)d_in[7];
    float* out = (float*)d_out;

    float *XT, *XP;
    __nv_bfloat16 *W0h, *W0l, *Wch, *Wcl, *Hh, *Hl;
    unsigned* bar;
    cudaGetSymbolAddress((void**)&XT,  g_XT);
    cudaGetSymbolAddress((void**)&XP,  g_XP);
    cudaGetSymbolAddress((void**)&W0h, g_W0h);
    cudaGetSymbolAddress((void**)&W0l, g_W0l);
    cudaGetSymbolAddress((void**)&Wch, g_Wch);
    cudaGetSymbolAddress((void**)&Wcl, g_Wcl);
    cudaGetSymbolAddress((void**)&Hh,  g_Hh);
    cudaGetSymbolAddress((void**)&Hl,  g_Hl);
    cudaGetSymbolAddress((void**)&bar, g_bar);

    static int smem_set = 0;
    if (!smem_set) {
        cudaFuncSetAttribute(wave_kernel, cudaFuncAttributeMaxDynamicSharedMemorySize,
                             SMEM_BYTES);
        smem_set = 1;
    }

    cudaMemsetAsync(bar, 0, sizeof(unsigned));

    transpose_x<<<(T_ * B_ * (I_ / 4)) / 256, 256>>>(x, XT);

    // layer-0 input projection (fp32, K=64): XP = XT @ W_ih0^T + b_ih0
    gemm_nt<128, 64, 16, 8, 4><<<dim3(H_ / 64, (T_ * B_) / 128), 256>>>(
        XT, W_ih0, b_ih0, XP, T_ * B_, H_, I_);

    // weight splits
    split_w0<<<(H_ * H_) / 256, 256>>>(W_hh, W0h, W0l);
    build_wcat<<<(3 * H_ * K2_) / 256, 256>>>(W_ihr, W_hh, Wch, Wcl);

    // wavefront over all layers/time
    wave_kernel<<<128, 256, SMEM_BYTES>>>(XP, b_ihr);

    // final FC from h^{L-1}_{T-1} (parity (T-1)&1 = 1)
    fc_kernel<<<B_, 256>>>(Hh + (size_t)(3 * 2 + 1) * BH_,
                           Hl + (size_t)(3 * 2 + 1) * BH_, W_fc, b_fc, out);
}